// round 5
// baseline (speedup 1.0000x reference)
#include <cuda_runtime.h>
#include <math.h>

// Problem dims (fixed by the dataset)
#define LL 2048
#define BB 32
#define HH 128
#define PP 256
#define ROWS (LL*BB)          // 65536
#define NCHUNK 32
#define CHLEN 64              // NCHUNK*CHLEN == LL

typedef unsigned long long u64;

// -------- scratch (device globals; no runtime allocation allowed) ----------
__device__ float g_bu_r[ROWS*PP];   // Bu real, later o real (in place)
__device__ float g_bu_i[ROWS*PP];
__device__ float g_Bbr[PP*HH];
__device__ float g_Bbi[PP*HH];
__device__ float g_Ar[PP], g_Ai[PP];          // A = exp(Lambda_bar)
__device__ float g_A64r[PP], g_A64i[PP];      // A^CHLEN
__device__ float g_carry_r[NCHUNK*BB*PP], g_carry_i[NCHUNK*BB*PP];
__device__ float g_pre_r[NCHUNK*BB*PP],  g_pre_i[NCHUNK*BB*PP];

// -------- packed f32x2 helpers (sm_103a FFMA2 path) ------------------------
__device__ __forceinline__ float2 upk2(u64 v) {
    float2 f;
    asm("mov.b64 {%0,%1}, %2;" : "=f"(f.x), "=f"(f.y) : "l"(v));
    return f;
}
__device__ __forceinline__ u64 f2fma(u64 a, u64 b, u64 c) {
    u64 d;
    asm("fma.rn.f32x2 %0, %1, %2, %3;" : "=l"(d) : "l"(a), "l"(b), "l"(c));
    return d;
}

// ---------------------------------------------------------------------------
// Setup: per-p discretization constants + B_bar = ((A-1)/lam) * B_tilde
// ---------------------------------------------------------------------------
__global__ void setup_kernel(const float* __restrict__ logLr,
                             const float* __restrict__ Li,
                             const float* __restrict__ Btr,
                             const float* __restrict__ Bti,
                             const float* __restrict__ logDelta)
{
    int p = threadIdx.x;   // 256 threads
    float lamR = -expf(logLr[p]);
    float lamI = Li[p];
    float dt   = expf(logDelta[p]);
    float llr  = lamR * dt;
    float lli  = lamI * dt;

    float s, c;
    float er = expf(llr);
    sincosf(lli, &s, &c);
    float Ar = er * c, Ai = er * s;
    g_Ar[p] = Ar; g_Ai[p] = Ai;

    float e64 = expf((float)CHLEN * llr);
    sincosf((float)CHLEN * lli, &s, &c);
    g_A64r[p] = e64 * c;
    g_A64i[p] = e64 * s;

    // (A - 1) / lam
    float fr = Ar - 1.0f, fi = Ai;
    float den = lamR*lamR + lamI*lamI;
    float inv = 1.0f / den;
    float br = (fr*lamR + fi*lamI) * inv;
    float bi = (fi*lamR - fr*lamI) * inv;

    for (int h = 0; h < HH; h++) {
        float tr = Btr[p*HH + h];
        float ti = Bti[p*HH + h];
        g_Bbr[p*HH + h] = br*tr - bi*ti;
        g_Bbi[p*HH + h] = br*ti + bi*tr;
    }
}

// ---------------------------------------------------------------------------
// GEMM1 (f32x2): Bu[row][p] = sum_h u[row][h] * Bbar[p][h]
// Block tile 64 rows x 128 p, 256 threads, 4(row)x8(p) micro-tile.
// acc[i][j] is a packed f32x2: lane0 = real, lane1 = imag.
//   a operand: dup(u) stored pre-duplicated in smem (broadcast LDS)
//   b operand: (Bbr, Bbi) pairs, split into 4 arrays for conflict-free LDS.128
// ---------------------------------------------------------------------------
__global__ void __launch_bounds__(256) gemm1_kernel(const float* __restrict__ u)
{
    __shared__ __align__(16) float2 sA[8][64];       // (u,u) dup per row
    __shared__ __align__(16) float2 sB[4][8][32];    // (br,bi) pairs, q-split

    int rb = blockIdx.x * 64;
    int pb = blockIdx.y * 128;
    int tid = threadIdx.x;
    int tn = tid & 15;        // p micro index (8 cols each)
    int tm = tid >> 4;        // row micro index (4 rows each)

    u64 acc[4][8];
    #pragma unroll
    for (int i = 0; i < 4; i++)
        #pragma unroll
        for (int j = 0; j < 8; j++) acc[i][j] = 0ull;

    for (int k0 = 0; k0 < HH; k0 += 8) {
        // fill sA: 512 u values, duplicated
        #pragma unroll
        for (int it = 0; it < 2; it++) {
            int lin = tid + it*256;
            int k = lin & 7;
            int m = lin >> 3;
            float v = u[(rb+m)*HH + k0 + k];
            sA[k][m] = make_float2(v, v);
        }
        // fill sB: 1024 (br,bi) pairs
        #pragma unroll
        for (int it = 0; it < 4; it++) {
            int lin = tid + it*256;
            int k = lin & 7;
            int n = lin >> 3;                 // 0..127
            int col = pb + n;
            float br = g_Bbr[col*HH + k0 + k];
            float bi = g_Bbi[col*HH + k0 + k];
            int tnn = n >> 3;
            int w = n & 7;
            sB[w >> 1][k][tnn*2 + (w & 1)] = make_float2(br, bi);
        }
        __syncthreads();

        #pragma unroll
        for (int k = 0; k < 8; k++) {
            const u64* ap = (const u64*)&sA[k][tm*4];
            u64 a0 = ap[0], a1 = ap[1], a2 = ap[2], a3 = ap[3];
            u64 b[8];
            #pragma unroll
            for (int q = 0; q < 4; q++) {
                const u64* bp = (const u64*)&sB[q][k][tn*2];
                b[q*2+0] = bp[0];
                b[q*2+1] = bp[1];
            }
            #pragma unroll
            for (int j = 0; j < 8; j++) {
                acc[0][j] = f2fma(a0, b[j], acc[0][j]);
                acc[1][j] = f2fma(a1, b[j], acc[1][j]);
                acc[2][j] = f2fma(a2, b[j], acc[2][j]);
                acc[3][j] = f2fma(a3, b[j], acc[3][j]);
            }
        }
        __syncthreads();
    }

    #pragma unroll
    for (int i = 0; i < 4; i++) {
        int row = rb + tm*4 + i;
        float r0[8], i0[8];
        #pragma unroll
        for (int j = 0; j < 8; j++) {
            float2 v = upk2(acc[i][j]);
            r0[j] = v.x; i0[j] = v.y;
        }
        int p = pb + tn*8;
        *(float4*)&g_bu_r[row*PP + p    ] = make_float4(r0[0], r0[1], r0[2], r0[3]);
        *(float4*)&g_bu_r[row*PP + p + 4] = make_float4(r0[4], r0[5], r0[6], r0[7]);
        *(float4*)&g_bu_i[row*PP + p    ] = make_float4(i0[0], i0[1], i0[2], i0[3]);
        *(float4*)&g_bu_i[row*PP + p + 4] = make_float4(i0[4], i0[5], i0[6], i0[7]);
    }
}

// ---------------------------------------------------------------------------
// Scan pass 1: chunk-local scan (init 0), in place; store chunk-final state
// ---------------------------------------------------------------------------
__global__ void __launch_bounds__(256) scan1_kernel()
{
    int g = blockIdx.x * 256 + threadIdx.x;
    int p = g & 255;
    int b = (g >> 8) & 31;
    int c = g >> 13;

    float Ar = g_Ar[p], Ai = g_Ai[p];
    float sr = 0.f, si = 0.f;
    int idx = ((c*CHLEN)*BB + b)*PP + p;
    #pragma unroll 4
    for (int j = 0; j < CHLEN; j++) {
        float br = g_bu_r[idx];
        float bi = g_bu_i[idx];
        float nr = fmaf(Ar, sr, fmaf(-Ai, si, br));
        float ni = fmaf(Ar, si, fmaf( Ai, sr, bi));
        g_bu_r[idx] = nr;
        g_bu_i[idx] = ni;
        sr = nr; si = ni;
        idx += BB*PP;
    }
    int ci = (c*BB + b)*PP + p;
    g_carry_r[ci] = sr;
    g_carry_i[ci] = si;
}

// ---------------------------------------------------------------------------
// Scan pass 2: combine carries across chunks (serial over NCHUNK per seq)
// ---------------------------------------------------------------------------
__global__ void __launch_bounds__(256) scan2_kernel()
{
    int g = blockIdx.x * 256 + threadIdx.x;  // 8192 threads
    int p = g & 255;
    int b = g >> 8;
    float Ar = g_A64r[p], Ai = g_A64i[p];
    float sr = 0.f, si = 0.f;
    for (int c = 0; c < NCHUNK; c++) {
        int idx = (c*BB + b)*PP + p;
        g_pre_r[idx] = sr;
        g_pre_i[idx] = si;
        float cr = g_carry_r[idx];
        float ci = g_carry_i[idx];
        float nr = fmaf(Ar, sr, fmaf(-Ai, si, cr));
        float ni = fmaf(Ar, si, fmaf( Ai, sr, ci));
        sr = nr; si = ni;
    }
}

// ---------------------------------------------------------------------------
// Scan pass 3: apply cross-chunk correction  o[t] += A^(j+1) * prefix[c]
// ---------------------------------------------------------------------------
__global__ void __launch_bounds__(256) scan3_kernel()
{
    int g = blockIdx.x * 256 + threadIdx.x;
    int p = g & 255;
    int b = (g >> 8) & 31;
    int c = g >> 13;
    if (c == 0) return;   // whole block uniform in c -> no divergence

    int pidx = (c*BB + b)*PP + p;
    float pr = g_pre_r[pidx];
    float pi = g_pre_i[pidx];
    float Ar = g_Ar[p], Ai = g_Ai[p];
    float pwr = Ar, pwi = Ai;   // A^1

    int idx = ((c*CHLEN)*BB + b)*PP + p;
    #pragma unroll 4
    for (int j = 0; j < CHLEN; j++) {
        g_bu_r[idx] = fmaf(pwr, pr, fmaf(-pwi, pi, g_bu_r[idx]));
        g_bu_i[idx] = fmaf(pwr, pi, fmaf( pwi, pr, g_bu_i[idx]));
        float npwr = pwr*Ar - pwi*Ai;
        pwi = pwr*Ai + pwi*Ar;
        pwr = npwr;
        idx += BB*PP;
    }
}

// ---------------------------------------------------------------------------
// GEMM2 (f32x2): out[row][h] = sum_p ( or*Cr[h][p] - oi*Ci[h][p] ) + D[h]*u
// Block tile 64 rows x 128 h (all of H), K=PP in slabs of 8.
// acc[i][j] packed: lane0 accumulates or*cr, lane1 accumulates oi*(-ci);
// final value = lane0 + lane1.
// ---------------------------------------------------------------------------
__global__ void __launch_bounds__(256) gemm2_kernel(const float* __restrict__ u,
                                                    const float* __restrict__ Cr,
                                                    const float* __restrict__ Ci,
                                                    const float* __restrict__ Dv,
                                                    float* __restrict__ out)
{
    __shared__ __align__(16) float2 sA[8][64];       // (or, oi) per row
    __shared__ __align__(16) float2 sB[4][8][32];    // (cr, -ci) pairs, q-split

    int rb = blockIdx.x * 64;
    int tid = threadIdx.x;
    int tn = tid & 15;       // h micro index (8 cols each)
    int tm = tid >> 4;       // row micro index (4 rows each)

    u64 acc[4][8];
    #pragma unroll
    for (int i = 0; i < 4; i++)
        #pragma unroll
        for (int j = 0; j < 8; j++) acc[i][j] = 0ull;

    for (int k0 = 0; k0 < PP; k0 += 8) {
        #pragma unroll
        for (int it = 0; it < 2; it++) {
            int lin = tid + it*256;
            int k = lin & 7;
            int m = lin >> 3;
            int idx = (rb+m)*PP + k0 + k;
            sA[k][m] = make_float2(g_bu_r[idx], g_bu_i[idx]);
        }
        #pragma unroll
        for (int it = 0; it < 4; it++) {
            int lin = tid + it*256;
            int k = lin & 7;
            int n = lin >> 3;                 // h = n (HH == 128)
            float cr =  Cr[n*PP + k0 + k];
            float ci = -Ci[n*PP + k0 + k];
            int tnn = n >> 3;
            int w = n & 7;
            sB[w >> 1][k][tnn*2 + (w & 1)] = make_float2(cr, ci);
        }
        __syncthreads();

        #pragma unroll
        for (int k = 0; k < 8; k++) {
            const u64* ap = (const u64*)&sA[k][tm*4];
            u64 a0 = ap[0], a1 = ap[1], a2 = ap[2], a3 = ap[3];
            u64 b[8];
            #pragma unroll
            for (int q = 0; q < 4; q++) {
                const u64* bp = (const u64*)&sB[q][k][tn*2];
                b[q*2+0] = bp[0];
                b[q*2+1] = bp[1];
            }
            #pragma unroll
            for (int j = 0; j < 8; j++) {
                acc[0][j] = f2fma(a0, b[j], acc[0][j]);
                acc[1][j] = f2fma(a1, b[j], acc[1][j]);
                acc[2][j] = f2fma(a2, b[j], acc[2][j]);
                acc[3][j] = f2fma(a3, b[j], acc[3][j]);
            }
        }
        __syncthreads();
    }

    int h0 = tn*8;
    float4 d0 = *(const float4*)&Dv[h0];
    float4 d1 = *(const float4*)&Dv[h0 + 4];
    float dv[8] = {d0.x, d0.y, d0.z, d0.w, d1.x, d1.y, d1.z, d1.w};

    #pragma unroll
    for (int i = 0; i < 4; i++) {
        int row = rb + tm*4 + i;
        float4 u0 = *(const float4*)&u[row*HH + h0];
        float4 u1 = *(const float4*)&u[row*HH + h0 + 4];
        float uv[8] = {u0.x, u0.y, u0.z, u0.w, u1.x, u1.y, u1.z, u1.w};
        float r[8];
        #pragma unroll
        for (int j = 0; j < 8; j++) {
            float2 v = upk2(acc[i][j]);
            r[j] = fmaf(dv[j], uv[j], v.x + v.y);
        }
        *(float4*)&out[row*HH + h0    ] = make_float4(r[0], r[1], r[2], r[3]);
        *(float4*)&out[row*HH + h0 + 4] = make_float4(r[4], r[5], r[6], r[7]);
    }
}

// ---------------------------------------------------------------------------
extern "C" void kernel_launch(void* const* d_in, const int* in_sizes, int n_in,
                              void* d_out, int out_size)
{
    const float* u        = (const float*)d_in[0];
    const float* logLr    = (const float*)d_in[1];
    const float* Li       = (const float*)d_in[2];
    const float* Btr      = (const float*)d_in[3];
    const float* Bti      = (const float*)d_in[4];
    const float* Cr       = (const float*)d_in[5];
    const float* Ci       = (const float*)d_in[6];
    const float* Dv       = (const float*)d_in[7];
    const float* logDelta = (const float*)d_in[8];
    float* out = (float*)d_out;

    setup_kernel<<<1, 256>>>(logLr, Li, Btr, Bti, logDelta);
    gemm1_kernel<<<dim3(ROWS/64, PP/128), 256>>>(u);
    scan1_kernel<<<(NCHUNK*BB*PP)/256, 256>>>();
    scan2_kernel<<<(BB*PP)/256, 256>>>();
    scan3_kernel<<<(NCHUNK*BB*PP)/256, 256>>>();
    gemm2_kernel<<<ROWS/64, 256>>>(u, Cr, Ci, Dv, out);
}

// round 15
// speedup vs baseline: 1.2869x; 1.2869x over previous
#include <cuda_runtime.h>
#include <cuda_bf16.h>
#include <math.h>
#include <cstdint>

// Problem dims (fixed by the dataset)
#define LL 2048
#define BB 32
#define HH 128
#define PP 256
#define ROWS (LL*BB)          // 65536
#define NCHUNK 32
#define CHLEN 64              // NCHUNK*CHLEN == LL

// -------- scratch (device globals; no runtime allocation allowed) ----------
__device__ float g_bu_r[ROWS*PP];   // Bu real, later o real (in place)
__device__ float g_bu_i[ROWS*PP];
__device__ float g_Bbr[PP*HH];
__device__ float g_Bbi[PP*HH];
__device__ float g_Ar[PP], g_Ai[PP];          // A = exp(Lambda_bar)
__device__ float g_A64r[PP], g_A64i[PP];      // A^CHLEN
__device__ float g_carry_r[NCHUNK*BB*PP], g_carry_i[NCHUNK*BB*PP];
__device__ float g_pre_r[NCHUNK*BB*PP],  g_pre_i[NCHUNK*BB*PP];

// ======================= mma.sync helpers (base PTX, sm_80+) ===============
__device__ __forceinline__ uint32_t smem_u32(const void* p) {
    uint32_t a;
    asm("{ .reg .u64 t; cvta.to.shared.u64 t, %1; cvt.u32.u64 %0, t; }" : "=r"(a) : "l"(p));
    return a;
}

#define LDM_X4(r, addr) \
    asm volatile("ldmatrix.sync.aligned.m8n8.x4.shared.b16 {%0,%1,%2,%3}, [%4];" \
        : "=r"((r)[0]), "=r"((r)[1]), "=r"((r)[2]), "=r"((r)[3]) : "r"(addr))
#define LDM_X2(r, addr) \
    asm volatile("ldmatrix.sync.aligned.m8n8.x2.shared.b16 {%0,%1}, [%2];" \
        : "=r"((r)[0]), "=r"((r)[1]) : "r"(addr))

__device__ __forceinline__ void mma16816(float* c, const uint32_t* a, const uint32_t* b) {
    asm volatile(
        "mma.sync.aligned.m16n8k16.row.col.f32.bf16.bf16.f32 "
        "{%0,%1,%2,%3}, {%4,%5,%6,%7}, {%8,%9}, {%0,%1,%2,%3};"
        : "+f"(c[0]), "+f"(c[1]), "+f"(c[2]), "+f"(c[3])
        : "r"(a[0]), "r"(a[1]), "r"(a[2]), "r"(a[3]), "r"(b[0]), "r"(b[1]));
}

// split-bf16 convert: 4 floats -> hi[4], lo[4] (packed as 2x u32 each)
__device__ __forceinline__ void cvt4(__nv_bfloat16* hip, __nv_bfloat16* lop,
                                     float4 v, float sgn) {
    float f[4] = {v.x * sgn, v.y * sgn, v.z * sgn, v.w * sgn};
    uint32_t hp[2], lp[2];
    #pragma unroll
    for (int q = 0; q < 2; q++) {
        __nv_bfloat16 h0 = __float2bfloat16(f[q*2+0]);
        __nv_bfloat16 h1 = __float2bfloat16(f[q*2+1]);
        __nv_bfloat16 l0 = __float2bfloat16(f[q*2+0] - __bfloat162float(h0));
        __nv_bfloat16 l1 = __float2bfloat16(f[q*2+1] - __bfloat162float(h1));
        hp[q] = ((uint32_t)__bfloat16_as_ushort(h1) << 16) | __bfloat16_as_ushort(h0);
        lp[q] = ((uint32_t)__bfloat16_as_ushort(l1) << 16) | __bfloat16_as_ushort(l0);
    }
    ((uint32_t*)hip)[0] = hp[0]; ((uint32_t*)hip)[1] = hp[1];
    ((uint32_t*)lop)[0] = lp[0]; ((uint32_t*)lop)[1] = lp[1];
}

#define SRS 136   // smem row stride in halves (128 + 8 pad -> ldmatrix conflict-free)

// ---------------------------------------------------------------------------
// Setup: per-p discretization constants + B_bar = ((A-1)/lam) * B_tilde
// ---------------------------------------------------------------------------
__global__ void setup_kernel(const float* __restrict__ logLr,
                             const float* __restrict__ Li,
                             const float* __restrict__ Btr,
                             const float* __restrict__ Bti,
                             const float* __restrict__ logDelta)
{
    int p = threadIdx.x;   // 256 threads
    float lamR = -expf(logLr[p]);
    float lamI = Li[p];
    float dt   = expf(logDelta[p]);
    float llr  = lamR * dt;
    float lli  = lamI * dt;

    float s, c;
    float er = expf(llr);
    sincosf(lli, &s, &c);
    float Ar = er * c, Ai = er * s;
    g_Ar[p] = Ar; g_Ai[p] = Ai;

    float e64 = expf((float)CHLEN * llr);
    sincosf((float)CHLEN * lli, &s, &c);
    g_A64r[p] = e64 * c;
    g_A64i[p] = e64 * s;

    float fr = Ar - 1.0f, fi = Ai;
    float den = lamR*lamR + lamI*lamI;
    float inv = 1.0f / den;
    float br = (fr*lamR + fi*lamI) * inv;
    float bi = (fi*lamR - fr*lamI) * inv;

    for (int h = 0; h < HH; h++) {
        float tr = Btr[p*HH + h];
        float ti = Bti[p*HH + h];
        g_Bbr[p*HH + h] = br*tr - bi*ti;
        g_Bbi[p*HH + h] = br*ti + bi*tr;
    }
}

// ---------------------------------------------------------------------------
// GEMM1 (HMMA split-bf16): Bu[row][p] = sum_h u[row][h] * Bbar[p][h]
// CTA tile: M=128 rows x N=64 cols of W = [Bbr; Bbi] (512 rows).
// grid = (512, 8). 8 warps as 4(m) x 2(n); warp tile 32x32.
// smem halves: Ahi[128][136], Alo, Bhi[64][136], Blo  -> 104448 B
// ---------------------------------------------------------------------------
#define G1_ALO (128*SRS)
#define G1_BHI (2*128*SRS)
#define G1_BLO (2*128*SRS + 64*SRS)
#define G1_SMEM ((2*128*SRS + 2*64*SRS) * 2)

__global__ void __launch_bounds__(256) gemm1_mma(const float* __restrict__ u)
{
    extern __shared__ __nv_bfloat16 sm[];
    __nv_bfloat16* Ahi = sm;
    __nv_bfloat16* Alo = sm + G1_ALO;
    __nv_bfloat16* Bhi = sm + G1_BHI;
    __nv_bfloat16* Blo = sm + G1_BLO;

    int tid = threadIdx.x, lane = tid & 31, wid = tid >> 5;
    int wm = wid >> 1, wn = wid & 1;
    int rb = blockIdx.x * 128;
    int nb = blockIdx.y;          // 0..7 (0-3: Bbr, 4-7: Bbi)

    // convert A: u rows [rb, rb+128), K=128
    for (int i = tid; i < 128*32; i += 256) {
        int row = i >> 5, c4 = (i & 31) * 4;
        float4 v = *(const float4*)&u[(size_t)(rb + row) * HH + c4];
        cvt4(Ahi + row*SRS + c4, Alo + row*SRS + c4, v, 1.0f);
    }
    // convert B: 64 rows of W
    const float* Wsrc = (nb < 4) ? g_Bbr + (size_t)nb * 64 * HH
                                 : g_Bbi + (size_t)(nb - 4) * 64 * HH;
    for (int i = tid; i < 64*32; i += 256) {
        int row = i >> 5, c4 = (i & 31) * 4;
        float4 v = *(const float4*)&Wsrc[(size_t)row * HH + c4];
        cvt4(Bhi + row*SRS + c4, Blo + row*SRS + c4, v, 1.0f);
    }
    __syncthreads();

    float acc[2][4][4];
    #pragma unroll
    for (int mi = 0; mi < 2; mi++)
        #pragma unroll
        for (int ni = 0; ni < 4; ni++)
            #pragma unroll
            for (int q = 0; q < 4; q++) acc[mi][ni][q] = 0.f;

    int r16 = lane & 15, c8 = (lane >> 4) * 8;
    int rB = lane & 7,  cB = ((lane >> 3) & 1) * 8;

    #pragma unroll
    for (int term = 0; term < 3; term++) {
        const __nv_bfloat16* At = (term == 2) ? Alo : Ahi;
        const __nv_bfloat16* Bt = (term == 1) ? Blo : Bhi;
        #pragma unroll
        for (int k0 = 0; k0 < 128; k0 += 16) {
            uint32_t a[2][4];
            #pragma unroll
            for (int mi = 0; mi < 2; mi++)
                LDM_X4(a[mi], smem_u32(At + (wm*32 + mi*16 + r16)*SRS + k0 + c8));
            #pragma unroll
            for (int ni = 0; ni < 4; ni++) {
                uint32_t b[2];
                LDM_X2(b, smem_u32(Bt + (wn*32 + ni*8 + rB)*SRS + k0 + cB));
                mma16816(acc[0][ni], a[0], b);
                mma16816(acc[1][ni], a[1], b);
            }
        }
    }

    // epilogue: C frag c0,c1 -> (row, col..col+1), c2,c3 -> (row+8, ..)
    float* dst = (nb < 4) ? g_bu_r : g_bu_i;
    int ncol0 = (nb & 3) * 64 + wn * 32;
    int rowt = lane >> 2, colt = (lane & 3) * 2;
    #pragma unroll
    for (int mi = 0; mi < 2; mi++)
        #pragma unroll
        for (int ni = 0; ni < 4; ni++) {
            int row = rb + wm*32 + mi*16 + rowt;
            int col = ncol0 + ni*8 + colt;
            *(float2*)&dst[(size_t)row * PP + col] =
                make_float2(acc[mi][ni][0], acc[mi][ni][1]);
            *(float2*)&dst[(size_t)(row + 8) * PP + col] =
                make_float2(acc[mi][ni][2], acc[mi][ni][3]);
        }
}

// ---------------------------------------------------------------------------
// Scan pass 1: chunk-local scan (init 0), in place; store chunk-final state
// ---------------------------------------------------------------------------
__global__ void __launch_bounds__(256) scan1_kernel()
{
    int g = blockIdx.x * 256 + threadIdx.x;
    int p = g & 255;
    int b = (g >> 8) & 31;
    int c = g >> 13;

    float Ar = g_Ar[p], Ai = g_Ai[p];
    float sr = 0.f, si = 0.f;
    int idx = ((c*CHLEN)*BB + b)*PP + p;
    #pragma unroll 4
    for (int j = 0; j < CHLEN; j++) {
        float br = g_bu_r[idx];
        float bi = g_bu_i[idx];
        float nr = fmaf(Ar, sr, fmaf(-Ai, si, br));
        float ni = fmaf(Ar, si, fmaf( Ai, sr, bi));
        g_bu_r[idx] = nr;
        g_bu_i[idx] = ni;
        sr = nr; si = ni;
        idx += BB*PP;
    }
    int ci = (c*BB + b)*PP + p;
    g_carry_r[ci] = sr;
    g_carry_i[ci] = si;
}

// ---------------------------------------------------------------------------
// Scan pass 2: combine carries (preload all 32 carries -> MLP=32)
// ---------------------------------------------------------------------------
__global__ void __launch_bounds__(256) scan2_kernel()
{
    int g = blockIdx.x * 256 + threadIdx.x;  // 8192 threads
    int p = g & 255;
    int b = g >> 8;
    float Ar = g_A64r[p], Ai = g_A64i[p];
    float cr[NCHUNK], ci[NCHUNK];
    #pragma unroll
    for (int c = 0; c < NCHUNK; c++) {
        int idx = (c*BB + b)*PP + p;
        cr[c] = g_carry_r[idx];
        ci[c] = g_carry_i[idx];
    }
    float sr = 0.f, si = 0.f;
    #pragma unroll
    for (int c = 0; c < NCHUNK; c++) {
        int idx = (c*BB + b)*PP + p;
        g_pre_r[idx] = sr;
        g_pre_i[idx] = si;
        float nr = fmaf(Ar, sr, fmaf(-Ai, si, cr[c]));
        float ni = fmaf(Ar, si, fmaf( Ai, sr, ci[c]));
        sr = nr; si = ni;
    }
}

// ---------------------------------------------------------------------------
// Scan pass 3: apply cross-chunk correction  o[t] += A^(j+1) * prefix[c]
// ---------------------------------------------------------------------------
__global__ void __launch_bounds__(256) scan3_kernel()
{
    int g = blockIdx.x * 256 + threadIdx.x;
    int p = g & 255;
    int b = (g >> 8) & 31;
    int c = g >> 13;
    if (c == 0) return;   // whole block uniform in c -> no divergence

    int pidx = (c*BB + b)*PP + p;
    float pr = g_pre_r[pidx];
    float pi = g_pre_i[pidx];
    float Ar = g_Ar[p], Ai = g_Ai[p];
    float pwr = Ar, pwi = Ai;   // A^1

    int idx = ((c*CHLEN)*BB + b)*PP + p;
    #pragma unroll 4
    for (int j = 0; j < CHLEN; j++) {
        g_bu_r[idx] = fmaf(pwr, pr, fmaf(-pwi, pi, g_bu_r[idx]));
        g_bu_i[idx] = fmaf(pwr, pi, fmaf( pwi, pr, g_bu_i[idx]));
        float npwr = pwr*Ar - pwi*Ai;
        pwi = pwr*Ai + pwi*Ar;
        pwr = npwr;
        idx += BB*PP;
    }
}

// ---------------------------------------------------------------------------
// GEMM2 (HMMA split-bf16): out[row][h] = sum_p or*Cr[h][p] - oi*Ci[h][p]
//                                         + D[h]*u[row][h]
// CTA tile: M=128, N=128 (all h). K=512 via 4 chunks of 128:
//   kc 0,1: A = o_r cols [0:128),[128:256),  B = Cr  (same col range)
//   kc 2,3: A = o_i,                         B = -Ci
// 8 warps 4(m) x 2(n); warp tile 32x64.
// smem halves: Ahi[128][136], Alo, Bhi[128][136], Blo -> 139264 B
// ---------------------------------------------------------------------------
#define G2_ALO (128*SRS)
#define G2_BHI (2*128*SRS)
#define G2_BLO (3*128*SRS)
#define G2_SMEM (4*128*SRS*2)

__global__ void __launch_bounds__(256) gemm2_mma(const float* __restrict__ u,
                                                 const float* __restrict__ Cr,
                                                 const float* __restrict__ Ci,
                                                 const float* __restrict__ Dv,
                                                 float* __restrict__ out)
{
    extern __shared__ __nv_bfloat16 sm[];
    __nv_bfloat16* Ahi = sm;
    __nv_bfloat16* Alo = sm + G2_ALO;
    __nv_bfloat16* Bhi = sm + G2_BHI;
    __nv_bfloat16* Blo = sm + G2_BLO;

    int tid = threadIdx.x, lane = tid & 31, wid = tid >> 5;
    int wm = wid >> 1, wn = wid & 1;
    int rb = blockIdx.x * 128;

    float acc[2][8][4];
    #pragma unroll
    for (int mi = 0; mi < 2; mi++)
        #pragma unroll
        for (int ni = 0; ni < 8; ni++)
            #pragma unroll
            for (int q = 0; q < 4; q++) acc[mi][ni][q] = 0.f;

    int r16 = lane & 15, c8 = (lane >> 4) * 8;
    int rB = lane & 7,  cB = ((lane >> 3) & 1) * 8;

    for (int kc = 0; kc < 4; kc++) {
        const float* Asrc = (kc < 2) ? g_bu_r : g_bu_i;
        const float* Bsrc = (kc < 2) ? Cr : Ci;
        float sgn = (kc < 2) ? 1.0f : -1.0f;
        int pc = (kc & 1) * 128;

        for (int i = tid; i < 128*32; i += 256) {
            int row = i >> 5, c4 = (i & 31) * 4;
            float4 va = *(const float4*)&Asrc[(size_t)(rb + row) * PP + pc + c4];
            cvt4(Ahi + row*SRS + c4, Alo + row*SRS + c4, va, 1.0f);
            float4 vb = *(const float4*)&Bsrc[(size_t)row * PP + pc + c4];
            cvt4(Bhi + row*SRS + c4, Blo + row*SRS + c4, vb, sgn);
        }
        __syncthreads();

        #pragma unroll
        for (int term = 0; term < 3; term++) {
            const __nv_bfloat16* At = (term == 2) ? Alo : Ahi;
            const __nv_bfloat16* Bt = (term == 1) ? Blo : Bhi;
            #pragma unroll
            for (int k0 = 0; k0 < 128; k0 += 16) {
                uint32_t a[2][4];
                #pragma unroll
                for (int mi = 0; mi < 2; mi++)
                    LDM_X4(a[mi], smem_u32(At + (wm*32 + mi*16 + r16)*SRS + k0 + c8));
                #pragma unroll
                for (int ni = 0; ni < 8; ni++) {
                    uint32_t b[2];
                    LDM_X2(b, smem_u32(Bt + (wn*64 + ni*8 + rB)*SRS + k0 + cB));
                    mma16816(acc[0][ni], a[0], b);
                    mma16816(acc[1][ni], a[1], b);
                }
            }
        }
        __syncthreads();
    }

    // epilogue: + D*u, store
    int rowt = lane >> 2, colt = (lane & 3) * 2;
    #pragma unroll
    for (int mi = 0; mi < 2; mi++)
        #pragma unroll
        for (int ni = 0; ni < 8; ni++) {
            int row = rb + wm*32 + mi*16 + rowt;
            int h   = wn*64 + ni*8 + colt;
            float2 d2 = *(const float2*)&Dv[h];
            float2 u0 = *(const float2*)&u[(size_t)row * HH + h];
            float2 u1 = *(const float2*)&u[(size_t)(row + 8) * HH + h];
            *(float2*)&out[(size_t)row * HH + h] = make_float2(
                fmaf(d2.x, u0.x, acc[mi][ni][0]), fmaf(d2.y, u0.y, acc[mi][ni][1]));
            *(float2*)&out[(size_t)(row + 8) * HH + h] = make_float2(
                fmaf(d2.x, u1.x, acc[mi][ni][2]), fmaf(d2.y, u1.y, acc[mi][ni][3]));
        }
}

// ---------------------------------------------------------------------------
extern "C" void kernel_launch(void* const* d_in, const int* in_sizes, int n_in,
                              void* d_out, int out_size)
{
    const float* u        = (const float*)d_in[0];
    const float* logLr    = (const float*)d_in[1];
    const float* Li       = (const float*)d_in[2];
    const float* Btr      = (const float*)d_in[3];
    const float* Bti      = (const float*)d_in[4];
    const float* Cr       = (const float*)d_in[5];
    const float* Ci       = (const float*)d_in[6];
    const float* Dv       = (const float*)d_in[7];
    const float* logDelta = (const float*)d_in[8];
    float* out = (float*)d_out;

    cudaFuncSetAttribute(gemm1_mma, cudaFuncAttributeMaxDynamicSharedMemorySize, G1_SMEM);
    cudaFuncSetAttribute(gemm2_mma, cudaFuncAttributeMaxDynamicSharedMemorySize, G2_SMEM);

    setup_kernel<<<1, 256>>>(logLr, Li, Btr, Bti, logDelta);
    gemm1_mma<<<dim3(ROWS/128, 8), 256, G1_SMEM>>>(u);
    scan1_kernel<<<(NCHUNK*BB*PP)/256, 256>>>();
    scan2_kernel<<<(BB*PP)/256, 256>>>();
    scan3_kernel<<<(NCHUNK*BB*PP)/256, 256>>>();
    gemm2_mma<<<ROWS/128, 256, G2_SMEM>>>(u, Cr, Ci, Dv, out);
}

// round 16
// speedup vs baseline: 1.6102x; 1.2512x over previous
#include <cuda_runtime.h>
#include <cuda_bf16.h>
#include <math.h>
#include <cstdint>

// Problem dims (fixed by the dataset)
#define LL 2048
#define BB 32
#define HH 128
#define PP 256
#define ROWS (LL*BB)          // 65536
#define NCHUNK 32
#define CHLEN 64              // NCHUNK*CHLEN == LL

// -------- scratch (device globals; no runtime allocation allowed) ----------
__device__ float g_bu_r[ROWS*PP];   // Bu real, later o_local real (in place)
__device__ float g_bu_i[ROWS*PP];
__device__ float g_Bbr[PP*HH];
__device__ float g_Bbi[PP*HH];
__device__ float g_Ar[PP], g_Ai[PP];          // A = exp(Lambda_bar)
__device__ float g_A64r[PP], g_A64i[PP];      // A^CHLEN
__device__ float g_Apr[CHLEN*PP], g_Api[CHLEN*PP];  // Apow[j][p] = A^(j+1)
__device__ float g_carry_r[NCHUNK*BB*PP], g_carry_i[NCHUNK*BB*PP];
__device__ float g_pre_r[NCHUNK*BB*PP],  g_pre_i[NCHUNK*BB*PP];

// ======================= mma.sync helpers (base PTX, sm_80+) ===============
__device__ __forceinline__ uint32_t smem_u32(const void* p) {
    uint32_t a;
    asm("{ .reg .u64 t; cvta.to.shared.u64 t, %1; cvt.u32.u64 %0, t; }" : "=r"(a) : "l"(p));
    return a;
}

#define LDM_X4(r, addr) \
    asm volatile("ldmatrix.sync.aligned.m8n8.x4.shared.b16 {%0,%1,%2,%3}, [%4];" \
        : "=r"((r)[0]), "=r"((r)[1]), "=r"((r)[2]), "=r"((r)[3]) : "r"(addr))
#define LDM_X2(r, addr) \
    asm volatile("ldmatrix.sync.aligned.m8n8.x2.shared.b16 {%0,%1}, [%2];" \
        : "=r"((r)[0]), "=r"((r)[1]) : "r"(addr))

__device__ __forceinline__ void mma16816(float* c, const uint32_t* a, const uint32_t* b) {
    asm volatile(
        "mma.sync.aligned.m16n8k16.row.col.f32.bf16.bf16.f32 "
        "{%0,%1,%2,%3}, {%4,%5,%6,%7}, {%8,%9}, {%0,%1,%2,%3};"
        : "+f"(c[0]), "+f"(c[1]), "+f"(c[2]), "+f"(c[3])
        : "r"(a[0]), "r"(a[1]), "r"(a[2]), "r"(a[3]), "r"(b[0]), "r"(b[1]));
}

// split-bf16 convert: 4 floats -> hi[4], lo[4] (packed as 2x u32 each)
__device__ __forceinline__ void cvt4(__nv_bfloat16* hip, __nv_bfloat16* lop,
                                     float4 v, float sgn) {
    float f[4] = {v.x * sgn, v.y * sgn, v.z * sgn, v.w * sgn};
    uint32_t hp[2], lp[2];
    #pragma unroll
    for (int q = 0; q < 2; q++) {
        __nv_bfloat16 h0 = __float2bfloat16(f[q*2+0]);
        __nv_bfloat16 h1 = __float2bfloat16(f[q*2+1]);
        __nv_bfloat16 l0 = __float2bfloat16(f[q*2+0] - __bfloat162float(h0));
        __nv_bfloat16 l1 = __float2bfloat16(f[q*2+1] - __bfloat162float(h1));
        hp[q] = ((uint32_t)__bfloat16_as_ushort(h1) << 16) | __bfloat16_as_ushort(h0);
        lp[q] = ((uint32_t)__bfloat16_as_ushort(l1) << 16) | __bfloat16_as_ushort(l0);
    }
    ((uint32_t*)hip)[0] = hp[0]; ((uint32_t*)hip)[1] = hp[1];
    ((uint32_t*)lop)[0] = lp[0]; ((uint32_t*)lop)[1] = lp[1];
}

#define SRS 136   // smem row stride in halves (128 + 8 pad -> ldmatrix conflict-free)

// ---------------------------------------------------------------------------
// Setup: discretization constants, B_bar, and A-power table A^1..A^64
// ---------------------------------------------------------------------------
__global__ void setup_kernel(const float* __restrict__ logLr,
                             const float* __restrict__ Li,
                             const float* __restrict__ Btr,
                             const float* __restrict__ Bti,
                             const float* __restrict__ logDelta)
{
    int p = threadIdx.x;   // 256 threads
    float lamR = -expf(logLr[p]);
    float lamI = Li[p];
    float dt   = expf(logDelta[p]);
    float llr  = lamR * dt;
    float lli  = lamI * dt;

    float s, c;
    float er = expf(llr);
    sincosf(lli, &s, &c);
    float Ar = er * c, Ai = er * s;
    g_Ar[p] = Ar; g_Ai[p] = Ai;

    float e64 = expf((float)CHLEN * llr);
    sincosf((float)CHLEN * lli, &s, &c);
    g_A64r[p] = e64 * c;
    g_A64i[p] = e64 * s;

    // power table: g_Ap[j][p] = A^(j+1), j = 0..63
    float pwr = Ar, pwi = Ai;
    for (int jj = 0; jj < CHLEN; jj++) {
        g_Apr[jj*PP + p] = pwr;
        g_Api[jj*PP + p] = pwi;
        float n = pwr*Ar - pwi*Ai;
        pwi = pwr*Ai + pwi*Ar;
        pwr = n;
    }

    float fr = Ar - 1.0f, fi = Ai;
    float den = lamR*lamR + lamI*lamI;
    float inv = 1.0f / den;
    float br = (fr*lamR + fi*lamI) * inv;
    float bi = (fi*lamR - fr*lamI) * inv;

    for (int h = 0; h < HH; h++) {
        float tr = Btr[p*HH + h];
        float ti = Bti[p*HH + h];
        g_Bbr[p*HH + h] = br*tr - bi*ti;
        g_Bbi[p*HH + h] = br*ti + bi*tr;
    }
}

// ---------------------------------------------------------------------------
// GEMM1 (HMMA split-bf16): Bu[row][p] = sum_h u[row][h] * Bbar[p][h]
// CTA: 128 rows; A converted ONCE, then loop over 8 N-tiles of 64 W-rows
// (W = [Bbr; Bbi], 512 rows). grid = 512. 8 warps 4(m)x2(n), warp tile 32x32.
// ---------------------------------------------------------------------------
#define G1_ALO (128*SRS)
#define G1_BHI (2*128*SRS)
#define G1_BLO (2*128*SRS + 64*SRS)
#define G1_SMEM ((2*128*SRS + 2*64*SRS) * 2)

__global__ void __launch_bounds__(256) gemm1_mma(const float* __restrict__ u)
{
    extern __shared__ __nv_bfloat16 sm[];
    __nv_bfloat16* Ahi = sm;
    __nv_bfloat16* Alo = sm + G1_ALO;
    __nv_bfloat16* Bhi = sm + G1_BHI;
    __nv_bfloat16* Blo = sm + G1_BLO;

    int tid = threadIdx.x, lane = tid & 31, wid = tid >> 5;
    int wm = wid >> 1, wn = wid & 1;
    int rb = blockIdx.x * 128;

    // convert A once: u rows [rb, rb+128), K=128
    for (int i = tid; i < 128*32; i += 256) {
        int row = i >> 5, c4 = (i & 31) * 4;
        float4 v = *(const float4*)&u[(size_t)(rb + row) * HH + c4];
        cvt4(Ahi + row*SRS + c4, Alo + row*SRS + c4, v, 1.0f);
    }

    int r16 = lane & 15, c8 = (lane >> 4) * 8;
    int rB = lane & 7,  cB = ((lane >> 3) & 1) * 8;
    int rowt = lane >> 2, colt = (lane & 3) * 2;

    for (int nb = 0; nb < 8; nb++) {
        // convert B tile: 64 rows of W
        const float* Wsrc = (nb < 4) ? g_Bbr + (size_t)nb * 64 * HH
                                     : g_Bbi + (size_t)(nb - 4) * 64 * HH;
        for (int i = tid; i < 64*32; i += 256) {
            int row = i >> 5, c4 = (i & 31) * 4;
            float4 v = *(const float4*)&Wsrc[(size_t)row * HH + c4];
            cvt4(Bhi + row*SRS + c4, Blo + row*SRS + c4, v, 1.0f);
        }
        __syncthreads();

        float acc[2][4][4];
        #pragma unroll
        for (int mi = 0; mi < 2; mi++)
            #pragma unroll
            for (int ni = 0; ni < 4; ni++)
                #pragma unroll
                for (int q = 0; q < 4; q++) acc[mi][ni][q] = 0.f;

        #pragma unroll
        for (int term = 0; term < 3; term++) {
            const __nv_bfloat16* At = (term == 2) ? Alo : Ahi;
            const __nv_bfloat16* Bt = (term == 1) ? Blo : Bhi;
            #pragma unroll
            for (int k0 = 0; k0 < 128; k0 += 16) {
                uint32_t a[2][4];
                #pragma unroll
                for (int mi = 0; mi < 2; mi++)
                    LDM_X4(a[mi], smem_u32(At + (wm*32 + mi*16 + r16)*SRS + k0 + c8));
                #pragma unroll
                for (int ni = 0; ni < 4; ni++) {
                    uint32_t b[2];
                    LDM_X2(b, smem_u32(Bt + (wn*32 + ni*8 + rB)*SRS + k0 + cB));
                    mma16816(acc[0][ni], a[0], b);
                    mma16816(acc[1][ni], a[1], b);
                }
            }
        }

        // epilogue for this nb
        float* dst = (nb < 4) ? g_bu_r : g_bu_i;
        int ncol0 = (nb & 3) * 64 + wn * 32;
        #pragma unroll
        for (int mi = 0; mi < 2; mi++)
            #pragma unroll
            for (int ni = 0; ni < 4; ni++) {
                int row = rb + wm*32 + mi*16 + rowt;
                int col = ncol0 + ni*8 + colt;
                *(float2*)&dst[(size_t)row * PP + col] =
                    make_float2(acc[mi][ni][0], acc[mi][ni][1]);
                *(float2*)&dst[(size_t)(row + 8) * PP + col] =
                    make_float2(acc[mi][ni][2], acc[mi][ni][3]);
            }
        __syncthreads();   // protect B tile before next nb overwrites it
    }
}

// ---------------------------------------------------------------------------
// Scan pass 1: chunk-local scan (init 0), in place; store chunk-final state
// ---------------------------------------------------------------------------
__global__ void __launch_bounds__(256) scan1_kernel()
{
    int g = blockIdx.x * 256 + threadIdx.x;
    int p = g & 255;
    int b = (g >> 8) & 31;
    int c = g >> 13;

    float Ar = g_Ar[p], Ai = g_Ai[p];
    float sr = 0.f, si = 0.f;
    int idx = ((c*CHLEN)*BB + b)*PP + p;
    #pragma unroll 4
    for (int j = 0; j < CHLEN; j++) {
        float br = g_bu_r[idx];
        float bi = g_bu_i[idx];
        float nr = fmaf(Ar, sr, fmaf(-Ai, si, br));
        float ni = fmaf(Ar, si, fmaf( Ai, sr, bi));
        g_bu_r[idx] = nr;
        g_bu_i[idx] = ni;
        sr = nr; si = ni;
        idx += BB*PP;
    }
    int ci = (c*BB + b)*PP + p;
    g_carry_r[ci] = sr;
    g_carry_i[ci] = si;
}

// ---------------------------------------------------------------------------
// Scan pass 2: combine carries (preload all 32 carries -> MLP=32)
// ---------------------------------------------------------------------------
__global__ void __launch_bounds__(256) scan2_kernel()
{
    int g = blockIdx.x * 256 + threadIdx.x;  // 8192 threads
    int p = g & 255;
    int b = g >> 8;
    float Ar = g_A64r[p], Ai = g_A64i[p];
    float cr[NCHUNK], ci[NCHUNK];
    #pragma unroll
    for (int c = 0; c < NCHUNK; c++) {
        int idx = (c*BB + b)*PP + p;
        cr[c] = g_carry_r[idx];
        ci[c] = g_carry_i[idx];
    }
    float sr = 0.f, si = 0.f;
    #pragma unroll
    for (int c = 0; c < NCHUNK; c++) {
        int idx = (c*BB + b)*PP + p;
        g_pre_r[idx] = sr;
        g_pre_i[idx] = si;
        float nr = fmaf(Ar, sr, fmaf(-Ai, si, cr[c]));
        float ni = fmaf(Ar, si, fmaf( Ai, sr, ci[c]));
        sr = nr; si = ni;
    }
}

// ---------------------------------------------------------------------------
// GEMM2 (HMMA split-bf16, fused scan3): out[row][h] = sum_p o*C + D*u where
// o = o_local + A^(j+1)*prefix[c] is applied on the fly during A-conversion.
// row -> t = row>>5, b = row&31, j = t&63, c = t>>6; pre[c==0] is zero.
// CTA: M=128, N=128, K=512 via 4 chunks (kc 0,1: o_r x Cr; kc 2,3: o_i x -Ci).
// ---------------------------------------------------------------------------
#define G2_ALO (128*SRS)
#define G2_BHI (2*128*SRS)
#define G2_BLO (3*128*SRS)
#define G2_SMEM (4*128*SRS*2)

__global__ void __launch_bounds__(256) gemm2_mma(const float* __restrict__ u,
                                                 const float* __restrict__ Cr,
                                                 const float* __restrict__ Ci,
                                                 const float* __restrict__ Dv,
                                                 float* __restrict__ out)
{
    extern __shared__ __nv_bfloat16 sm[];
    __nv_bfloat16* Ahi = sm;
    __nv_bfloat16* Alo = sm + G2_ALO;
    __nv_bfloat16* Bhi = sm + G2_BHI;
    __nv_bfloat16* Blo = sm + G2_BLO;

    int tid = threadIdx.x, lane = tid & 31, wid = tid >> 5;
    int wm = wid >> 1, wn = wid & 1;
    int rb = blockIdx.x * 128;

    float acc[2][8][4];
    #pragma unroll
    for (int mi = 0; mi < 2; mi++)
        #pragma unroll
        for (int ni = 0; ni < 8; ni++)
            #pragma unroll
            for (int q = 0; q < 4; q++) acc[mi][ni][q] = 0.f;

    int r16 = lane & 15, c8 = (lane >> 4) * 8;
    int rB = lane & 7,  cB = ((lane >> 3) & 1) * 8;

    for (int kc = 0; kc < 4; kc++) {
        const float* Asrc = (kc < 2) ? g_bu_r : g_bu_i;
        const float* Bsrc = (kc < 2) ? Cr : Ci;
        float sgn = (kc < 2) ? 1.0f : -1.0f;
        bool isReal = (kc < 2);
        int pc = (kc & 1) * 128;

        for (int i = tid; i < 128*32; i += 256) {
            int rin = i >> 5, c4 = (i & 31) * 4;
            int row = rb + rin;
            int t = row >> 5, b = row & 31;
            int j = t & (CHLEN-1), cc = t >> 6;
            int pp4 = pc + c4;

            float4 o4 = *(const float4*)&Asrc[(size_t)row * PP + pp4];
            float4 apr = *(const float4*)&g_Apr[j*PP + pp4];
            float4 api = *(const float4*)&g_Api[j*PP + pp4];
            int pidx = (cc*BB + b)*PP + pp4;
            float4 pr4 = *(const float4*)&g_pre_r[pidx];
            float4 pi4 = *(const float4*)&g_pre_i[pidx];

            float4 va;
            if (isReal) {
                va.x = o4.x + apr.x*pr4.x - api.x*pi4.x;
                va.y = o4.y + apr.y*pr4.y - api.y*pi4.y;
                va.z = o4.z + apr.z*pr4.z - api.z*pi4.z;
                va.w = o4.w + apr.w*pr4.w - api.w*pi4.w;
            } else {
                va.x = o4.x + apr.x*pi4.x + api.x*pr4.x;
                va.y = o4.y + apr.y*pi4.y + api.y*pr4.y;
                va.z = o4.z + apr.z*pi4.z + api.z*pr4.z;
                va.w = o4.w + apr.w*pi4.w + api.w*pr4.w;
            }
            cvt4(Ahi + rin*SRS + c4, Alo + rin*SRS + c4, va, 1.0f);

            float4 vb = *(const float4*)&Bsrc[(size_t)rin * PP + pp4];
            cvt4(Bhi + rin*SRS + c4, Blo + rin*SRS + c4, vb, sgn);
        }
        __syncthreads();

        #pragma unroll
        for (int term = 0; term < 3; term++) {
            const __nv_bfloat16* At = (term == 2) ? Alo : Ahi;
            const __nv_bfloat16* Bt = (term == 1) ? Blo : Bhi;
            #pragma unroll
            for (int k0 = 0; k0 < 128; k0 += 16) {
                uint32_t a[2][4];
                #pragma unroll
                for (int mi = 0; mi < 2; mi++)
                    LDM_X4(a[mi], smem_u32(At + (wm*32 + mi*16 + r16)*SRS + k0 + c8));
                #pragma unroll
                for (int ni = 0; ni < 8; ni++) {
                    uint32_t b[2];
                    LDM_X2(b, smem_u32(Bt + (wn*64 + ni*8 + rB)*SRS + k0 + cB));
                    mma16816(acc[0][ni], a[0], b);
                    mma16816(acc[1][ni], a[1], b);
                }
            }
        }
        __syncthreads();
    }

    // epilogue: + D*u, store
    int rowt = lane >> 2, colt = (lane & 3) * 2;
    #pragma unroll
    for (int mi = 0; mi < 2; mi++)
        #pragma unroll
        for (int ni = 0; ni < 8; ni++) {
            int row = rb + wm*32 + mi*16 + rowt;
            int h   = wn*64 + ni*8 + colt;
            float2 d2 = *(const float2*)&Dv[h];
            float2 u0 = *(const float2*)&u[(size_t)row * HH + h];
            float2 u1 = *(const float2*)&u[(size_t)(row + 8) * HH + h];
            *(float2*)&out[(size_t)row * HH + h] = make_float2(
                fmaf(d2.x, u0.x, acc[mi][ni][0]), fmaf(d2.y, u0.y, acc[mi][ni][1]));
            *(float2*)&out[(size_t)(row + 8) * HH + h] = make_float2(
                fmaf(d2.x, u1.x, acc[mi][ni][2]), fmaf(d2.y, u1.y, acc[mi][ni][3]));
        }
}

// ---------------------------------------------------------------------------
extern "C" void kernel_launch(void* const* d_in, const int* in_sizes, int n_in,
                              void* d_out, int out_size)
{
    const float* u        = (const float*)d_in[0];
    const float* logLr    = (const float*)d_in[1];
    const float* Li       = (const float*)d_in[2];
    const float* Btr      = (const float*)d_in[3];
    const float* Bti      = (const float*)d_in[4];
    const float* Cr       = (const float*)d_in[5];
    const float* Ci       = (const float*)d_in[6];
    const float* Dv       = (const float*)d_in[7];
    const float* logDelta = (const float*)d_in[8];
    float* out = (float*)d_out;

    cudaFuncSetAttribute(gemm1_mma, cudaFuncAttributeMaxDynamicSharedMemorySize, G1_SMEM);
    cudaFuncSetAttribute(gemm2_mma, cudaFuncAttributeMaxDynamicSharedMemorySize, G2_SMEM);

    setup_kernel<<<1, 256>>>(logLr, Li, Btr, Bti, logDelta);
    gemm1_mma<<<ROWS/128, 256, G1_SMEM>>>(u);
    scan1_kernel<<<(NCHUNK*BB*PP)/256, 256>>>();
    scan2_kernel<<<(BB*PP)/256, 256>>>();
    gemm2_mma<<<ROWS/128, 256, G2_SMEM>>>(u, Cr, Ci, Dv, out);
}